// round 1
// baseline (speedup 1.0000x reference)
#include <cuda_runtime.h>
#include <cuda_bf16.h>
#include <cstdint>

// Problem-size upper bounds (fixed by the dataset)
#define MAXE 500000
#define MAXN 100000
#define CC   128

// ---------------- scratch (device globals; no allocation) ----------------
__device__ float g_lift[(size_t)MAXE * CC];          // lift_aggr [E,128]
__device__ float g_hpre[(size_t)MAXE * CC];          // lvl1 pre-BN; reused as edge out_pre
__device__ float g_hidden[(size_t)MAXE * 2 * CC];    // MLP hidden (edge size >= node size)
__device__ float g_lvl[(size_t)MAXN * CC];           // lvl_aggr [N,128]
__device__ float g_outpre_n[(size_t)MAXN * CC];      // node out pre-BN
__device__ float g_stat_sum[5 * 256];
__device__ float g_stat_sq[5 * 256];
__device__ float g_aff_a[5 * 256];
__device__ float g_aff_d[5 * 256];

// ---------------- lift: lift_aggr = node[s] + node[t] ----------------
__global__ void k_lift(const float* __restrict__ node, const int* __restrict__ ep, int E)
{
    int idx = blockIdx.x * blockDim.x + threadIdx.x;
    int total = E * 32;           // float4 per thread (128/4 = 32 per row)
    if (idx >= total) return;
    int e = idx >> 5;
    int c4 = idx & 31;
    int s = ep[e];
    int t = ep[E + e];
    float4 a = ((const float4*)node)[(size_t)s * 32 + c4];
    float4 b = ((const float4*)node)[(size_t)t * 32 + c4];
    a.x += b.x; a.y += b.y; a.z += b.z; a.w += b.w;
    ((float4*)g_lift)[idx] = a;
}

// ---------------- scatter: lvl_aggr[s] += h, lvl_aggr[t] += h ----------------
// h = relu(a*h_pre + d) computed on the fly (stage-0 affine).
__global__ void k_scatter(const int* __restrict__ ep, int E)
{
    int idx = blockIdx.x * blockDim.x + threadIdx.x;
    int total = E * 32;
    if (idx >= total) return;
    int e = idx >> 5;
    int c4 = (idx & 31) * 4;
    float4 v = *(const float4*)(g_hpre + (size_t)e * CC + c4);
    float4 a = *(const float4*)(g_aff_a + c4);
    float4 d = *(const float4*)(g_aff_d + c4);
    v.x = fmaxf(fmaf(a.x, v.x, d.x), 0.f);
    v.y = fmaxf(fmaf(a.y, v.y, d.y), 0.f);
    v.z = fmaxf(fmaf(a.z, v.z, d.z), 0.f);
    v.w = fmaxf(fmaf(a.w, v.w, d.w), 0.f);
    int s = ep[e];
    int t = ep[E + e];
    float* ps = g_lvl + (size_t)s * CC + c4;
    float* pt = g_lvl + (size_t)t * CC + c4;
    atomicAdd(ps + 0, v.x); atomicAdd(ps + 1, v.y); atomicAdd(ps + 2, v.z); atomicAdd(ps + 3, v.w);
    atomicAdd(pt + 0, v.x); atomicAdd(pt + 1, v.y); atomicAdd(pt + 2, v.z); atomicAdd(pt + 3, v.w);
}

// ---------------- fused GEMM + BN-stats epilogue ----------------
// Tile: BM=64 rows x 128 cols, BK=16, 256 threads, 8x4 accum per thread.
// mode 0: A = concat(A0[row,0:128], A1[row,0:128])          (K=256)
// mode 1: A = (1+*eps)*A0[row] + A1[row]                    (K=128)
// mode 2: A = relu(aIn[k]*A0[row,k] + dIn[k])               (K=256, stride K)
#define BM 64
#define BK 16

__global__ __launch_bounds__(256) void k_gemm(
    const float* __restrict__ A0, const float* __restrict__ A1,
    const float* __restrict__ W,  const float* __restrict__ eps_ptr,
    const float* __restrict__ aIn, const float* __restrict__ dIn,
    float* __restrict__ out, float* __restrict__ statSum, float* __restrict__ statSq,
    int M, int K, int NC, int mode)
{
    __shared__ float As[BM][BK + 4];   // [64][20]
    __shared__ float Bs[BK][128];
    __shared__ float ssum[128];
    __shared__ float ssq[128];

    const int tid = threadIdx.x;
    const int m_blk = blockIdx.x * BM;
    const int nb = blockIdx.y * 128;

    const int rg = tid >> 5;           // row group 0..7
    const int cg = tid & 31;           // col group 0..31
    const int m0 = rg * 8;
    const int n0 = cg * 4;

    const int lrow = tid >> 2;         // A-load row 0..63
    const int k4 = (tid & 3) * 4;      // A-load k offset

    float epsv = 0.f;
    if (mode == 1) epsv = 1.f + __ldg(eps_ptr);

    float4 acc[8];
#pragma unroll
    for (int i = 0; i < 8; i++) acc[i] = make_float4(0.f, 0.f, 0.f, 0.f);

    for (int kk = 0; kk < K; kk += BK) {
        // ---- load A chunk [64 x 16] ----
        float4 av = make_float4(0.f, 0.f, 0.f, 0.f);
        int gm = m_blk + lrow;
        if (gm < M) {
            int gk = kk + k4;
            if (mode == 0) {
                const float* src = (gk < 128) ? A0 : A1;
                int kloc = (gk < 128) ? gk : gk - 128;
                av = *(const float4*)(src + (size_t)gm * 128 + kloc);
            } else if (mode == 1) {
                float4 x = *(const float4*)(A0 + (size_t)gm * 128 + gk);
                float4 y = *(const float4*)(A1 + (size_t)gm * 128 + gk);
                av.x = fmaf(epsv, x.x, y.x);
                av.y = fmaf(epsv, x.y, y.y);
                av.z = fmaf(epsv, x.z, y.z);
                av.w = fmaf(epsv, x.w, y.w);
            } else {
                float4 x = *(const float4*)(A0 + (size_t)gm * K + gk);
                float4 a = *(const float4*)(aIn + gk);
                float4 d = *(const float4*)(dIn + gk);
                av.x = fmaxf(fmaf(a.x, x.x, d.x), 0.f);
                av.y = fmaxf(fmaf(a.y, x.y, d.y), 0.f);
                av.z = fmaxf(fmaf(a.z, x.z, d.z), 0.f);
                av.w = fmaxf(fmaf(a.w, x.w, d.w), 0.f);
            }
        }
        *(float4*)&As[lrow][k4] = av;

        // ---- load B chunk [16 x 128] from W ----
#pragma unroll
        for (int j = 0; j < 2; j++) {
            int f = tid * 2 + j;       // float4 id, 512 total
            int r = f >> 5;
            int c4f = (f & 31) * 4;
            float4 wv = *(const float4*)(W + (size_t)(kk + r) * NC + nb + c4f);
            *(float4*)&Bs[r][c4f] = wv;
        }
        __syncthreads();

        // ---- compute ----
#pragma unroll
        for (int k = 0; k < BK; k++) {
            float a[8];
#pragma unroll
            for (int i = 0; i < 8; i++) a[i] = As[m0 + i][k];
            float4 b4 = *(const float4*)&Bs[k][n0];
#pragma unroll
            for (int i = 0; i < 8; i++) {
                acc[i].x = fmaf(a[i], b4.x, acc[i].x);
                acc[i].y = fmaf(a[i], b4.y, acc[i].y);
                acc[i].z = fmaf(a[i], b4.z, acc[i].z);
                acc[i].w = fmaf(a[i], b4.w, acc[i].w);
            }
        }
        __syncthreads();
    }

    // ---- epilogue: store + column stats (masked rows carry zeros) ----
    for (int i = tid; i < 128; i += 256) { ssum[i] = 0.f; ssq[i] = 0.f; }
    __syncthreads();

    {
        float s0 = 0.f, q0 = 0.f, s1 = 0.f, q1 = 0.f, s2 = 0.f, q2 = 0.f, s3 = 0.f, q3 = 0.f;
#pragma unroll
        for (int i = 0; i < 8; i++) {
            s0 += acc[i].x; q0 += acc[i].x * acc[i].x;
            s1 += acc[i].y; q1 += acc[i].y * acc[i].y;
            s2 += acc[i].z; q2 += acc[i].z * acc[i].z;
            s3 += acc[i].w; q3 += acc[i].w * acc[i].w;
        }
        atomicAdd(&ssum[n0 + 0], s0); atomicAdd(&ssq[n0 + 0], q0);
        atomicAdd(&ssum[n0 + 1], s1); atomicAdd(&ssq[n0 + 1], q1);
        atomicAdd(&ssum[n0 + 2], s2); atomicAdd(&ssq[n0 + 2], q2);
        atomicAdd(&ssum[n0 + 3], s3); atomicAdd(&ssq[n0 + 3], q3);
    }

#pragma unroll
    for (int i = 0; i < 8; i++) {
        int gm = m_blk + m0 + i;
        if (gm < M)
            *(float4*)(out + (size_t)gm * NC + nb + n0) = acc[i];
    }

    __syncthreads();
    for (int i = tid; i < 128; i += 256) {
        atomicAdd(&statSum[nb + i], ssum[i]);
        atomicAdd(&statSq[nb + i], ssq[i]);
    }
}

// ---------------- finalize BN stats -> affine (a, d) ----------------
__global__ void k_finalize(const float* __restrict__ sums, const float* __restrict__ sqs,
                           const float* __restrict__ g, const float* __restrict__ b,
                           float* __restrict__ aA, float* __restrict__ aD,
                           int ncols, float invM)
{
    int i = blockIdx.x * blockDim.x + threadIdx.x;
    if (i >= ncols) return;
    float mu = sums[i] * invM;
    float var = sqs[i] * invM - mu * mu;
    float rs = rsqrtf(var + 1e-5f);
    float a = g[i] * rs;
    aA[i] = a;
    aD[i] = fmaf(-mu, a, b[i]);
}

// ---------------- final normalize + ReLU -> d_out ----------------
__global__ void k_norm(const float* __restrict__ in,
                       const float* __restrict__ aA, const float* __restrict__ aD,
                       float* __restrict__ out, int M)
{
    int idx = blockIdx.x * blockDim.x + threadIdx.x;
    int total = M * 32;
    if (idx >= total) return;
    int c4 = (idx & 31) * 4;
    float4 v = ((const float4*)in)[idx];
    float4 a = *(const float4*)(aA + c4);
    float4 d = *(const float4*)(aD + c4);
    v.x = fmaxf(fmaf(a.x, v.x, d.x), 0.f);
    v.y = fmaxf(fmaf(a.y, v.y, d.y), 0.f);
    v.z = fmaxf(fmaf(a.z, v.z, d.z), 0.f);
    v.w = fmaxf(fmaf(a.w, v.w, d.w), 0.f);
    ((float4*)out)[idx] = v;
}

// ---------------- host launch ----------------
extern "C" void kernel_launch(void* const* d_in, const int* in_sizes, int n_in,
                              void* d_out, int out_size)
{
    const float* node   = (const float*)d_in[0];
    const float* edge   = (const float*)d_in[1];
    const int*   ep     = (const int*)  d_in[2];
    const float* W_lvl1 = (const float*)d_in[3];
    const float* gl1    = (const float*)d_in[4];
    const float* bl1    = (const float*)d_in[5];
    const float* W_n1   = (const float*)d_in[6];
    const float* gn1    = (const float*)d_in[7];
    const float* bn1    = (const float*)d_in[8];
    const float* W_n2   = (const float*)d_in[9];
    const float* gn2    = (const float*)d_in[10];
    const float* bn2    = (const float*)d_in[11];
    const float* W_e1   = (const float*)d_in[12];
    const float* ge1    = (const float*)d_in[13];
    const float* be1    = (const float*)d_in[14];
    const float* W_e2   = (const float*)d_in[15];
    const float* ge2    = (const float*)d_in[16];
    const float* be2    = (const float*)d_in[17];
    const float* eps1   = (const float*)d_in[18];
    const float* eps2   = (const float*)d_in[19];
    float* outp = (float*)d_out;

    const int Cc = in_sizes[4];                  // 128
    const int Nn = in_sizes[0] / Cc;
    const int Ee = in_sizes[1] / Cc;

    float *lift, *hpre, *hidden, *lvl, *outpre_n, *ssum, *ssq, *affA, *affD;
    cudaGetSymbolAddress((void**)&lift,     g_lift);
    cudaGetSymbolAddress((void**)&hpre,     g_hpre);
    cudaGetSymbolAddress((void**)&hidden,   g_hidden);
    cudaGetSymbolAddress((void**)&lvl,      g_lvl);
    cudaGetSymbolAddress((void**)&outpre_n, g_outpre_n);
    cudaGetSymbolAddress((void**)&ssum,     g_stat_sum);
    cudaGetSymbolAddress((void**)&ssq,      g_stat_sq);
    cudaGetSymbolAddress((void**)&affA,     g_aff_a);
    cudaGetSymbolAddress((void**)&affD,     g_aff_d);

    // zero accumulators (graph-capturable memset nodes)
    cudaMemsetAsync(lvl,  0, (size_t)Nn * Cc * sizeof(float), 0);
    cudaMemsetAsync(ssum, 0, 5 * 256 * sizeof(float), 0);
    cudaMemsetAsync(ssq,  0, 5 * 256 * sizeof(float), 0);

    const int TPB = 256;
    const int eThreads = Ee * 32;
    const int nThreads = Nn * 32;

    // 1) lift gather
    k_lift<<<(eThreads + TPB - 1) / TPB, TPB>>>(node, ep, Ee);

    // 2) lvl1 GEMM (concat) + stats stage 0
    dim3 gE((Ee + BM - 1) / BM, 1);
    k_gemm<<<gE, TPB>>>(lift, edge, W_lvl1, nullptr, nullptr, nullptr,
                        hpre, ssum + 0, ssq + 0, Ee, 256, 128, 0);
    k_finalize<<<1, 256>>>(ssum + 0, ssq + 0, gl1, bl1, affA + 0, affD + 0, 128, 1.f / (float)Ee);

    // 3) scatter-add h (affine+relu fused) into lvl_aggr
    k_scatter<<<(eThreads + TPB - 1) / TPB, TPB>>>(ep, Ee);

    // 4) node MLP
    dim3 gN1((Nn + BM - 1) / BM, 2);
    k_gemm<<<gN1, TPB>>>(node, lvl, W_n1, eps1, nullptr, nullptr,
                         hidden, ssum + 256, ssq + 256, Nn, 128, 256, 1);
    k_finalize<<<1, 256>>>(ssum + 256, ssq + 256, gn1, bn1, affA + 256, affD + 256, 256, 1.f / (float)Nn);
    dim3 gN2((Nn + BM - 1) / BM, 1);
    k_gemm<<<gN2, TPB>>>(hidden, nullptr, W_n2, nullptr, affA + 256, affD + 256,
                         outpre_n, ssum + 512, ssq + 512, Nn, 256, 128, 2);
    k_finalize<<<1, 256>>>(ssum + 512, ssq + 512, gn2, bn2, affA + 512, affD + 512, 128, 1.f / (float)Nn);
    k_norm<<<(nThreads + TPB - 1) / TPB, TPB>>>(outpre_n, affA + 512, affD + 512, outp, Nn);

    // 5) edge MLP (hidden buffer safely reused after node GEMM2 has consumed it)
    dim3 gE1((Ee + BM - 1) / BM, 2);
    k_gemm<<<gE1, TPB>>>(edge, lift, W_e1, eps2, nullptr, nullptr,
                         hidden, ssum + 768, ssq + 768, Ee, 128, 256, 1);
    k_finalize<<<1, 256>>>(ssum + 768, ssq + 768, ge1, be1, affA + 768, affD + 768, 256, 1.f / (float)Ee);
    dim3 gE2((Ee + BM - 1) / BM, 1);
    k_gemm<<<gE2, TPB>>>(hidden, nullptr, W_e2, nullptr, affA + 768, affD + 768,
                         hpre, ssum + 1024, ssq + 1024, Ee, 256, 128, 2);
    k_finalize<<<1, 256>>>(ssum + 1024, ssq + 1024, ge2, be2, affA + 1024, affD + 1024, 128, 1.f / (float)Ee);
    k_norm<<<(eThreads + TPB - 1) / TPB, TPB>>>(hpre, affA + 1024, affD + 1024,
                                                outp + (size_t)Nn * Cc, Ee);
}

// round 2
// speedup vs baseline: 1.6371x; 1.6371x over previous
#include <cuda_runtime.h>
#include <cuda_bf16.h>
#include <cstdint>

// Problem-size upper bounds (fixed by the dataset)
#define MAXE 500000
#define MAXN 100000
#define CC   128

// ---------------- scratch (device globals; no allocation) ----------------
__device__ float g_lift[(size_t)MAXE * CC];          // lift_aggr [E,128]
__device__ float g_hpre[(size_t)MAXE * CC];          // lvl1 pre-BN; reused as edge out_pre
__device__ float g_hidden[(size_t)MAXE * 2 * CC];    // MLP hidden (edge size >= node size)
__device__ float g_lvl[(size_t)MAXN * CC];           // lvl_aggr [N,128]
__device__ float g_outpre_n[(size_t)MAXN * CC];      // node out pre-BN
__device__ float g_stat_sum[5 * 256];
__device__ float g_stat_sq[5 * 256];
__device__ float g_aff_a[5 * 256];
__device__ float g_aff_d[5 * 256];

__device__ __forceinline__ uint32_t f2tf32(float x) {
    uint32_t r;
    asm("cvt.rna.tf32.f32 %0, %1;" : "=r"(r) : "f"(x));
    return r;
}

// ---------------- lift: lift_aggr = node[s] + node[t] ----------------
__global__ void k_lift(const float* __restrict__ node, const int* __restrict__ ep, int E)
{
    int idx = blockIdx.x * blockDim.x + threadIdx.x;
    int total = E * 32;
    if (idx >= total) return;
    int e = idx >> 5;
    int c4 = idx & 31;
    int s = ep[e];
    int t = ep[E + e];
    float4 a = ((const float4*)node)[(size_t)s * 32 + c4];
    float4 b = ((const float4*)node)[(size_t)t * 32 + c4];
    a.x += b.x; a.y += b.y; a.z += b.z; a.w += b.w;
    ((float4*)g_lift)[idx] = a;
}

// ---------------- scatter: lvl_aggr[s] += h, lvl_aggr[t] += h ----------------
__global__ void k_scatter(const int* __restrict__ ep, int E)
{
    int idx = blockIdx.x * blockDim.x + threadIdx.x;
    int total = E * 32;
    if (idx >= total) return;
    int e = idx >> 5;
    int c4 = (idx & 31) * 4;
    float4 v = *(const float4*)(g_hpre + (size_t)e * CC + c4);
    float4 a = *(const float4*)(g_aff_a + c4);
    float4 d = *(const float4*)(g_aff_d + c4);
    v.x = fmaxf(fmaf(a.x, v.x, d.x), 0.f);
    v.y = fmaxf(fmaf(a.y, v.y, d.y), 0.f);
    v.z = fmaxf(fmaf(a.z, v.z, d.z), 0.f);
    v.w = fmaxf(fmaf(a.w, v.w, d.w), 0.f);
    int s = ep[e];
    int t = ep[E + e];
    float* ps = g_lvl + (size_t)s * CC + c4;
    float* pt = g_lvl + (size_t)t * CC + c4;
    atomicAdd(ps + 0, v.x); atomicAdd(ps + 1, v.y); atomicAdd(ps + 2, v.z); atomicAdd(ps + 3, v.w);
    atomicAdd(pt + 0, v.x); atomicAdd(pt + 1, v.y); atomicAdd(pt + 2, v.z); atomicAdd(pt + 3, v.w);
}

// ---------------- fused tf32 tensor-core GEMM + BN-stats epilogue ----------------
// Block tile 128x128, BK=16, 256 threads (8 warps), warp tile 64x32 (m16n8k8).
// mode 0: A = concat(A0[row,0:128], A1[row,0:128])   (K=256)
// mode 1: A = (1+*eps)*A0[row] + A1[row]             (K=128)
// mode 2: A = relu(aIn[k]*A0[row,k] + dIn[k])        (row stride K)
#define BM 128
#define BN 128
#define BK 16

__global__ __launch_bounds__(256, 2) void k_gemm(
    const float* __restrict__ A0, const float* __restrict__ A1,
    const float* __restrict__ W,  const float* __restrict__ eps_ptr,
    const float* __restrict__ aIn, const float* __restrict__ dIn,
    float* __restrict__ out, float* __restrict__ statSum, float* __restrict__ statSq,
    int M, int K, int NC, int mode)
{
    __shared__ uint32_t As[BM][BK + 4];   // [128][20]
    __shared__ uint32_t Bs[BK][BN + 8];   // [16][136]
    __shared__ float ssum[BN];
    __shared__ float ssq[BN];

    const int tid    = threadIdx.x;
    const int warpId = tid >> 5;
    const int lane   = tid & 31;
    const int g      = lane >> 2;         // group 0..7
    const int t      = lane & 3;          // thread-in-group 0..3
    const int m0w    = (warpId >> 2) * 64;
    const int n0w    = (warpId & 3) * 32;
    const int m_blk  = blockIdx.x * BM;
    const int nb     = blockIdx.y * BN;

    float epsv = 0.f;
    if (mode == 1) epsv = 1.f + __ldg(eps_ptr);

    float acc[4][4][4];                   // [mtile][ntile][c0..c3]
#pragma unroll
    for (int i = 0; i < 4; i++)
#pragma unroll
        for (int j = 0; j < 4; j++)
#pragma unroll
            for (int c = 0; c < 4; c++) acc[i][j][c] = 0.f;

    for (int kk = 0; kk < K; kk += BK) {
        // ---- A chunk [128 x 16] : 2 float4 loads per thread ----
#pragma unroll
        for (int j = 0; j < 2; j++) {
            int f   = tid + j * 256;      // 0..511
            int row = f >> 2;             // 0..127
            int k4  = (f & 3) * 4;        // 0,4,8,12
            int gm  = m_blk + row;
            float4 av = make_float4(0.f, 0.f, 0.f, 0.f);
            if (gm < M) {
                int gk = kk + k4;
                if (mode == 0) {
                    const float* src = (gk < 128) ? A0 : A1;
                    int kloc = (gk < 128) ? gk : gk - 128;
                    av = *(const float4*)(src + (size_t)gm * 128 + kloc);
                } else if (mode == 1) {
                    float4 x = *(const float4*)(A0 + (size_t)gm * 128 + gk);
                    float4 y = *(const float4*)(A1 + (size_t)gm * 128 + gk);
                    av.x = fmaf(epsv, x.x, y.x);
                    av.y = fmaf(epsv, x.y, y.y);
                    av.z = fmaf(epsv, x.z, y.z);
                    av.w = fmaf(epsv, x.w, y.w);
                } else {
                    float4 x = *(const float4*)(A0 + (size_t)gm * K + gk);
                    float4 a = *(const float4*)(aIn + gk);
                    float4 d = *(const float4*)(dIn + gk);
                    av.x = fmaxf(fmaf(a.x, x.x, d.x), 0.f);
                    av.y = fmaxf(fmaf(a.y, x.y, d.y), 0.f);
                    av.z = fmaxf(fmaf(a.z, x.z, d.z), 0.f);
                    av.w = fmaxf(fmaf(a.w, x.w, d.w), 0.f);
                }
            }
            *(uint4*)&As[row][k4] = make_uint4(f2tf32(av.x), f2tf32(av.y),
                                               f2tf32(av.z), f2tf32(av.w));
        }
        // ---- B chunk [16 x 128] from W ----
#pragma unroll
        for (int j = 0; j < 2; j++) {
            int f   = tid + j * 256;
            int r   = f >> 5;             // 0..15
            int c4f = (f & 31) * 4;       // 0..124
            float4 wv = *(const float4*)(W + (size_t)(kk + r) * NC + nb + c4f);
            *(uint4*)&Bs[r][c4f] = make_uint4(f2tf32(wv.x), f2tf32(wv.y),
                                              f2tf32(wv.z), f2tf32(wv.w));
        }
        __syncthreads();

        // ---- compute: 2 x k8 steps ----
#pragma unroll
        for (int ks = 0; ks < 2; ks++) {
            const int kb = ks * 8;
            uint32_t af[4][4];
            uint32_t bf[4][2];
#pragma unroll
            for (int mt = 0; mt < 4; mt++) {
                int r = m0w + mt * 16 + g;
                af[mt][0] = As[r][kb + t];
                af[mt][1] = As[r + 8][kb + t];
                af[mt][2] = As[r][kb + t + 4];
                af[mt][3] = As[r + 8][kb + t + 4];
            }
#pragma unroll
            for (int nt = 0; nt < 4; nt++) {
                int c = n0w + nt * 8 + g;
                bf[nt][0] = Bs[kb + t][c];
                bf[nt][1] = Bs[kb + t + 4][c];
            }
#pragma unroll
            for (int mt = 0; mt < 4; mt++)
#pragma unroll
                for (int nt = 0; nt < 4; nt++) {
                    asm volatile(
                        "mma.sync.aligned.m16n8k8.row.col.f32.tf32.tf32.f32 "
                        "{%0,%1,%2,%3}, {%4,%5,%6,%7}, {%8,%9}, {%0,%1,%2,%3};"
                        : "+f"(acc[mt][nt][0]), "+f"(acc[mt][nt][1]),
                          "+f"(acc[mt][nt][2]), "+f"(acc[mt][nt][3])
                        : "r"(af[mt][0]), "r"(af[mt][1]), "r"(af[mt][2]), "r"(af[mt][3]),
                          "r"(bf[nt][0]), "r"(bf[nt][1]));
                }
        }
        __syncthreads();
    }

    // ---- epilogue: per-column stats + store ----
    for (int i = tid; i < BN; i += 256) { ssum[i] = 0.f; ssq[i] = 0.f; }
    __syncthreads();

#pragma unroll
    for (int nt = 0; nt < 4; nt++) {
        float se = 0.f, qe = 0.f, so = 0.f, qo = 0.f;
#pragma unroll
        for (int mt = 0; mt < 4; mt++) {
            float c0 = acc[mt][nt][0], c1 = acc[mt][nt][1];
            float c2 = acc[mt][nt][2], c3 = acc[mt][nt][3];
            se += c0 + c2; qe += c0 * c0 + c2 * c2;
            so += c1 + c3; qo += c1 * c1 + c3 * c3;
        }
        int ce = n0w + nt * 8 + 2 * t;
        atomicAdd(&ssum[ce], se);     atomicAdd(&ssq[ce], qe);
        atomicAdd(&ssum[ce + 1], so); atomicAdd(&ssq[ce + 1], qo);
    }

#pragma unroll
    for (int mt = 0; mt < 4; mt++) {
        int r0 = m_blk + m0w + mt * 16 + g;
        int r1 = r0 + 8;
#pragma unroll
        for (int nt = 0; nt < 4; nt++) {
            int ce = n0w + nt * 8 + 2 * t;
            if (r0 < M) {
                float2 v = make_float2(acc[mt][nt][0], acc[mt][nt][1]);
                *(float2*)(out + (size_t)r0 * NC + nb + ce) = v;
            }
            if (r1 < M) {
                float2 v = make_float2(acc[mt][nt][2], acc[mt][nt][3]);
                *(float2*)(out + (size_t)r1 * NC + nb + ce) = v;
            }
        }
    }

    __syncthreads();
    for (int i = tid; i < BN; i += 256) {
        atomicAdd(&statSum[nb + i], ssum[i]);
        atomicAdd(&statSq[nb + i], ssq[i]);
    }
}

// ---------------- finalize BN stats -> affine (a, d) ----------------
__global__ void k_finalize(const float* __restrict__ sums, const float* __restrict__ sqs,
                           const float* __restrict__ g, const float* __restrict__ b,
                           float* __restrict__ aA, float* __restrict__ aD,
                           int ncols, float invM)
{
    int i = blockIdx.x * blockDim.x + threadIdx.x;
    if (i >= ncols) return;
    float mu = sums[i] * invM;
    float var = sqs[i] * invM - mu * mu;
    float rs = rsqrtf(var + 1e-5f);
    float a = g[i] * rs;
    aA[i] = a;
    aD[i] = fmaf(-mu, a, b[i]);
}

// ---------------- final normalize + ReLU -> d_out ----------------
__global__ void k_norm(const float* __restrict__ in,
                       const float* __restrict__ aA, const float* __restrict__ aD,
                       float* __restrict__ out, int M)
{
    int idx = blockIdx.x * blockDim.x + threadIdx.x;
    int total = M * 32;
    if (idx >= total) return;
    int c4 = (idx & 31) * 4;
    float4 v = ((const float4*)in)[idx];
    float4 a = *(const float4*)(aA + c4);
    float4 d = *(const float4*)(aD + c4);
    v.x = fmaxf(fmaf(a.x, v.x, d.x), 0.f);
    v.y = fmaxf(fmaf(a.y, v.y, d.y), 0.f);
    v.z = fmaxf(fmaf(a.z, v.z, d.z), 0.f);
    v.w = fmaxf(fmaf(a.w, v.w, d.w), 0.f);
    ((float4*)out)[idx] = v;
}

// ---------------- host launch ----------------
extern "C" void kernel_launch(void* const* d_in, const int* in_sizes, int n_in,
                              void* d_out, int out_size)
{
    const float* node   = (const float*)d_in[0];
    const float* edge   = (const float*)d_in[1];
    const int*   ep     = (const int*)  d_in[2];
    const float* W_lvl1 = (const float*)d_in[3];
    const float* gl1    = (const float*)d_in[4];
    const float* bl1    = (const float*)d_in[5];
    const float* W_n1   = (const float*)d_in[6];
    const float* gn1    = (const float*)d_in[7];
    const float* bn1    = (const float*)d_in[8];
    const float* W_n2   = (const float*)d_in[9];
    const float* gn2    = (const float*)d_in[10];
    const float* bn2    = (const float*)d_in[11];
    const float* W_e1   = (const float*)d_in[12];
    const float* ge1    = (const float*)d_in[13];
    const float* be1    = (const float*)d_in[14];
    const float* W_e2   = (const float*)d_in[15];
    const float* ge2    = (const float*)d_in[16];
    const float* be2    = (const float*)d_in[17];
    const float* eps1   = (const float*)d_in[18];
    const float* eps2   = (const float*)d_in[19];
    float* outp = (float*)d_out;

    const int Cc = in_sizes[4];                  // 128
    const int Nn = in_sizes[0] / Cc;
    const int Ee = in_sizes[1] / Cc;

    float *lift, *hpre, *hidden, *lvl, *outpre_n, *ssum, *ssq, *affA, *affD;
    cudaGetSymbolAddress((void**)&lift,     g_lift);
    cudaGetSymbolAddress((void**)&hpre,     g_hpre);
    cudaGetSymbolAddress((void**)&hidden,   g_hidden);
    cudaGetSymbolAddress((void**)&lvl,      g_lvl);
    cudaGetSymbolAddress((void**)&outpre_n, g_outpre_n);
    cudaGetSymbolAddress((void**)&ssum,     g_stat_sum);
    cudaGetSymbolAddress((void**)&ssq,      g_stat_sq);
    cudaGetSymbolAddress((void**)&affA,     g_aff_a);
    cudaGetSymbolAddress((void**)&affD,     g_aff_d);

    cudaMemsetAsync(lvl,  0, (size_t)Nn * Cc * sizeof(float), 0);
    cudaMemsetAsync(ssum, 0, 5 * 256 * sizeof(float), 0);
    cudaMemsetAsync(ssq,  0, 5 * 256 * sizeof(float), 0);

    const int TPB = 256;
    const int eThreads = Ee * 32;
    const int nThreads = Nn * 32;

    // 1) lift gather
    k_lift<<<(eThreads + TPB - 1) / TPB, TPB>>>(node, ep, Ee);

    // 2) lvl1 GEMM (concat) + stats stage 0
    dim3 gE((Ee + BM - 1) / BM, 1);
    k_gemm<<<gE, TPB>>>(lift, edge, W_lvl1, nullptr, nullptr, nullptr,
                        hpre, ssum + 0, ssq + 0, Ee, 256, 128, 0);
    k_finalize<<<1, 256>>>(ssum + 0, ssq + 0, gl1, bl1, affA + 0, affD + 0, 128, 1.f / (float)Ee);

    // 3) scatter-add h (affine+relu fused) into lvl_aggr
    k_scatter<<<(eThreads + TPB - 1) / TPB, TPB>>>(ep, Ee);

    // 4) node MLP
    dim3 gN1((Nn + BM - 1) / BM, 2);
    k_gemm<<<gN1, TPB>>>(node, lvl, W_n1, eps1, nullptr, nullptr,
                         hidden, ssum + 256, ssq + 256, Nn, 128, 256, 1);
    k_finalize<<<1, 256>>>(ssum + 256, ssq + 256, gn1, bn1, affA + 256, affD + 256, 256, 1.f / (float)Nn);
    dim3 gN2((Nn + BM - 1) / BM, 1);
    k_gemm<<<gN2, TPB>>>(hidden, nullptr, W_n2, nullptr, affA + 256, affD + 256,
                         outpre_n, ssum + 512, ssq + 512, Nn, 256, 128, 2);
    k_finalize<<<1, 256>>>(ssum + 512, ssq + 512, gn2, bn2, affA + 512, affD + 512, 128, 1.f / (float)Nn);
    k_norm<<<(nThreads + TPB - 1) / TPB, TPB>>>(outpre_n, affA + 512, affD + 512, outp, Nn);

    // 5) edge MLP
    dim3 gE1((Ee + BM - 1) / BM, 2);
    k_gemm<<<gE1, TPB>>>(edge, lift, W_e1, eps2, nullptr, nullptr,
                         hidden, ssum + 768, ssq + 768, Ee, 128, 256, 1);
    k_finalize<<<1, 256>>>(ssum + 768, ssq + 768, ge1, be1, affA + 768, affD + 768, 256, 1.f / (float)Ee);
    dim3 gE2((Ee + BM - 1) / BM, 1);
    k_gemm<<<gE2, TPB>>>(hidden, nullptr, W_e2, nullptr, affA + 768, affD + 768,
                         hpre, ssum + 1024, ssq + 1024, Ee, 256, 128, 2);
    k_finalize<<<1, 256>>>(ssum + 1024, ssq + 1024, ge2, be2, affA + 1024, affD + 1024, 128, 1.f / (float)Ee);
    k_norm<<<(eThreads + TPB - 1) / TPB, TPB>>>(hpre, affA + 1024, affD + 1024,
                                                outp + (size_t)Nn * Cc, Ee);
}

// round 5
// speedup vs baseline: 1.6722x; 1.0214x over previous
#include <cuda_runtime.h>
#include <cuda_bf16.h>
#include <cstdint>

// Problem-size upper bounds (fixed by the dataset)
#define MAXE 500000
#define MAXN 100000
#define CC   128

// ---------------- scratch (device globals; no allocation) ----------------
__device__ float g_hpre[(size_t)MAXE * CC];          // lvl1 pre-BN; reused as edge out_pre
__device__ float g_hidden[(size_t)MAXE * 2 * CC];    // MLP hidden (edge size >= node size)
__device__ float g_lvl[(size_t)MAXN * CC];           // lvl_aggr [N,128]
__device__ float g_outpre_n[(size_t)MAXN * CC];      // node out pre-BN
__device__ float g_stat_sum[5 * 256];
__device__ float g_stat_sq[5 * 256];
__device__ float g_aff_a[5 * 256];
__device__ float g_aff_d[5 * 256];

__device__ __forceinline__ uint32_t f2tf32(float x) {
    uint32_t r;
    asm("cvt.rna.tf32.f32 %0, %1;" : "=r"(r) : "f"(x));
    return r;
}

// ---------------- scatter: lvl_aggr[s] += h, lvl_aggr[t] += h ----------------
// h = relu(a*h_pre + d) computed on the fly; vectorized red.v4
__global__ void k_scatter(const int* __restrict__ ep, int E)
{
    int idx = blockIdx.x * blockDim.x + threadIdx.x;
    int total = E * 32;
    if (idx >= total) return;
    int e = idx >> 5;
    int c4 = (idx & 31) * 4;
    float4 v = *(const float4*)(g_hpre + (size_t)e * CC + c4);
    float4 a = *(const float4*)(g_aff_a + c4);
    float4 d = *(const float4*)(g_aff_d + c4);
    v.x = fmaxf(fmaf(a.x, v.x, d.x), 0.f);
    v.y = fmaxf(fmaf(a.y, v.y, d.y), 0.f);
    v.z = fmaxf(fmaf(a.z, v.z, d.z), 0.f);
    v.w = fmaxf(fmaf(a.w, v.w, d.w), 0.f);
    int s = ep[e];
    int t = ep[E + e];
    float* ps = g_lvl + (size_t)s * CC + c4;
    float* pt = g_lvl + (size_t)t * CC + c4;
    asm volatile("red.global.add.v4.f32 [%0], {%1,%2,%3,%4};"
                 :: "l"(ps), "f"(v.x), "f"(v.y), "f"(v.z), "f"(v.w) : "memory");
    asm volatile("red.global.add.v4.f32 [%0], {%1,%2,%3,%4};"
                 :: "l"(pt), "f"(v.x), "f"(v.y), "f"(v.z), "f"(v.w) : "memory");
}

// ---------------- fused tf32 tensor-core GEMM + BN-stats epilogue ----------------
// Block tile 128x128, BK=16, 256 threads (8 warps), warp tile 64x32 (m16n8k8).
// Double-buffered smem; global loads for iter i+1 overlap MMAs of iter i.
// mode 0: A = concat(node[s]+node[t], edge[row])     (K=256, gathers)
// mode 1: A = (1+*eps)*A0[row] + A1[row]             (K=128)
// mode 2: A = relu(aIn[k]*A0[row,k] + dIn[k])        (row stride K)
// mode 3: A = (1+*eps)*edge[row] + node[s]+node[t]   (K=128, gathers)
#define BM 128
#define BN 128
#define BK 16

__global__ __launch_bounds__(256, 2) void k_gemm(
    const float* __restrict__ A0, const float* __restrict__ A1,
    const float* __restrict__ W,  const float* __restrict__ eps_ptr,
    const float* __restrict__ aIn, const float* __restrict__ dIn,
    const int* __restrict__ ep, int E,
    float* __restrict__ out, float* __restrict__ statSum, float* __restrict__ statSq,
    int M, int K, int NC, int mode)
{
    __shared__ uint32_t As[2][BM][BK + 4];   // 2*128*20*4 = 20.5 KB
    __shared__ uint32_t Bs[2][BK][BN + 8];   // 2*16*136*4 = 17.4 KB
    __shared__ float ssum[BN];
    __shared__ float ssq[BN];

    const int tid    = threadIdx.x;
    const int warpId = tid >> 5;
    const int lane   = tid & 31;
    const int g      = lane >> 2;
    const int t      = lane & 3;
    const int m0w    = (warpId >> 2) * 64;
    const int n0w    = (warpId & 3) * 32;
    const int m_blk  = blockIdx.x * BM;
    const int nb     = blockIdx.y * BN;

    // A-loader geometry (constant across K): thread serves rows f>>2, k-offset (f&3)*4
    int aRowL[2], aRowG[2], sIdx[2], tIdx[2];
    const int k4 = (tid & 3) * 4;
#pragma unroll
    for (int j = 0; j < 2; j++) {
        int f = tid + j * 256;
        aRowL[j] = f >> 2;
        int gm = m_blk + aRowL[j];
        aRowG[j] = gm;
        sIdx[j] = 0; tIdx[j] = 0;
        if ((mode == 0 || mode == 3) && gm < M) {
            sIdx[j] = ep[gm];
            tIdx[j] = ep[E + gm];
        }
    }
    // B-loader geometry
    int bRowL[2], bColL[2];
#pragma unroll
    for (int j = 0; j < 2; j++) {
        int f = tid + j * 256;
        bRowL[j] = f >> 5;
        bColL[j] = (f & 31) * 4;
    }

    float epsv = 0.f;
    if (mode == 1 || mode == 3) epsv = 1.f + __ldg(eps_ptr);

    float acc[4][4][4];
#pragma unroll
    for (int i = 0; i < 4; i++)
#pragma unroll
        for (int j = 0; j < 4; j++)
#pragma unroll
            for (int c = 0; c < 4; c++) acc[i][j][c] = 0.f;

    const int nIter = K / BK;
    float4 aPre[2], bPre[2];

    // ---- load tile (into registers) ----
    auto loadTile = [&](int it) {
#pragma unroll
        for (int j = 0; j < 2; j++) {
            float4 av = make_float4(0.f, 0.f, 0.f, 0.f);
            int gm = aRowG[j];
            if (gm < M) {
                int gk = it * BK + k4;
                if (mode == 0) {
                    if (gk < 128) {
                        float4 x = *(const float4*)(A0 + (size_t)sIdx[j] * 128 + gk);
                        float4 y = *(const float4*)(A0 + (size_t)tIdx[j] * 128 + gk);
                        av.x = x.x + y.x; av.y = x.y + y.y;
                        av.z = x.z + y.z; av.w = x.w + y.w;
                    } else {
                        av = *(const float4*)(A1 + (size_t)gm * 128 + (gk - 128));
                    }
                } else if (mode == 1) {
                    float4 x = *(const float4*)(A0 + (size_t)gm * 128 + gk);
                    float4 y = *(const float4*)(A1 + (size_t)gm * 128 + gk);
                    av.x = fmaf(epsv, x.x, y.x);
                    av.y = fmaf(epsv, x.y, y.y);
                    av.z = fmaf(epsv, x.z, y.z);
                    av.w = fmaf(epsv, x.w, y.w);
                } else if (mode == 2) {
                    float4 x = *(const float4*)(A0 + (size_t)gm * K + gk);
                    float4 a = *(const float4*)(aIn + gk);
                    float4 d = *(const float4*)(dIn + gk);
                    av.x = fmaxf(fmaf(a.x, x.x, d.x), 0.f);
                    av.y = fmaxf(fmaf(a.y, x.y, d.y), 0.f);
                    av.z = fmaxf(fmaf(a.z, x.z, d.z), 0.f);
                    av.w = fmaxf(fmaf(a.w, x.w, d.w), 0.f);
                } else { // mode 3
                    float4 eV = *(const float4*)(A0 + (size_t)gm * 128 + gk);
                    float4 x = *(const float4*)(A1 + (size_t)sIdx[j] * 128 + gk);
                    float4 y = *(const float4*)(A1 + (size_t)tIdx[j] * 128 + gk);
                    av.x = fmaf(epsv, eV.x, x.x + y.x);
                    av.y = fmaf(epsv, eV.y, x.y + y.y);
                    av.z = fmaf(epsv, eV.z, x.z + y.z);
                    av.w = fmaf(epsv, eV.w, x.w + y.w);
                }
            }
            aPre[j] = av;
            bPre[j] = *(const float4*)(W + (size_t)(it * BK + bRowL[j]) * NC + nb + bColL[j]);
        }
    };
    auto storeTile = [&](int buf) {
#pragma unroll
        for (int j = 0; j < 2; j++) {
            *(uint4*)&As[buf][aRowL[j]][k4] =
                make_uint4(f2tf32(aPre[j].x), f2tf32(aPre[j].y),
                           f2tf32(aPre[j].z), f2tf32(aPre[j].w));
            *(uint4*)&Bs[buf][bRowL[j]][bColL[j]] =
                make_uint4(f2tf32(bPre[j].x), f2tf32(bPre[j].y),
                           f2tf32(bPre[j].z), f2tf32(bPre[j].w));
        }
    };

    loadTile(0);
    storeTile(0);
    __syncthreads();

    for (int it = 0; it < nIter; it++) {
        const int buf = it & 1;
        if (it + 1 < nIter) loadTile(it + 1);   // overlap with MMAs below

#pragma unroll
        for (int ks = 0; ks < 2; ks++) {
            const int kb = ks * 8;
            uint32_t af[4][4];
            uint32_t bf[4][2];
#pragma unroll
            for (int mt = 0; mt < 4; mt++) {
                int r = m0w + mt * 16 + g;
                af[mt][0] = As[buf][r][kb + t];
                af[mt][1] = As[buf][r + 8][kb + t];
                af[mt][2] = As[buf][r][kb + t + 4];
                af[mt][3] = As[buf][r + 8][kb + t + 4];
            }
#pragma unroll
            for (int nt = 0; nt < 4; nt++) {
                int c = n0w + nt * 8 + g;
                bf[nt][0] = Bs[buf][kb + t][c];
                bf[nt][1] = Bs[buf][kb + t + 4][c];
            }
#pragma unroll
            for (int mt = 0; mt < 4; mt++)
#pragma unroll
                for (int nt = 0; nt < 4; nt++) {
                    asm volatile(
                        "mma.sync.aligned.m16n8k8.row.col.f32.tf32.tf32.f32 "
                        "{%0,%1,%2,%3}, {%4,%5,%6,%7}, {%8,%9}, {%0,%1,%2,%3};"
                        : "+f"(acc[mt][nt][0]), "+f"(acc[mt][nt][1]),
                          "+f"(acc[mt][nt][2]), "+f"(acc[mt][nt][3])
                        : "r"(af[mt][0]), "r"(af[mt][1]), "r"(af[mt][2]), "r"(af[mt][3]),
                          "r"(bf[nt][0]), "r"(bf[nt][1]));
                }
        }

        if (it + 1 < nIter) storeTile(buf ^ 1);
        __syncthreads();
    }

    // ---- epilogue: per-column stats + store ----
    for (int i = tid; i < BN; i += 256) { ssum[i] = 0.f; ssq[i] = 0.f; }
    __syncthreads();

#pragma unroll
    for (int nt = 0; nt < 4; nt++) {
        float se = 0.f, qe = 0.f, so = 0.f, qo = 0.f;
#pragma unroll
        for (int mt = 0; mt < 4; mt++) {
            float c0 = acc[mt][nt][0], c1 = acc[mt][nt][1];
            float c2 = acc[mt][nt][2], c3 = acc[mt][nt][3];
            se += c0 + c2; qe += c0 * c0 + c2 * c2;
            so += c1 + c3; qo += c1 * c1 + c3 * c3;
        }
        int ce = n0w + nt * 8 + 2 * t;
        atomicAdd(&ssum[ce], se);     atomicAdd(&ssq[ce], qe);
        atomicAdd(&ssum[ce + 1], so); atomicAdd(&ssq[ce + 1], qo);
    }

#pragma unroll
    for (int mt = 0; mt < 4; mt++) {
        int r0 = m_blk + m0w + mt * 16 + g;
        int r1 = r0 + 8;
#pragma unroll
        for (int nt = 0; nt < 4; nt++) {
            int ce = n0w + nt * 8 + 2 * t;
            if (r0 < M) {
                float2 v = make_float2(acc[mt][nt][0], acc[mt][nt][1]);
                *(float2*)(out + (size_t)r0 * NC + nb + ce) = v;
            }
            if (r1 < M) {
                float2 v = make_float2(acc[mt][nt][2], acc[mt][nt][3]);
                *(float2*)(out + (size_t)r1 * NC + nb + ce) = v;
            }
        }
    }

    __syncthreads();
    for (int i = tid; i < BN; i += 256) {
        atomicAdd(&statSum[nb + i], ssum[i]);
        atomicAdd(&statSq[nb + i], ssq[i]);
    }
}

// ---------------- finalize BN stats -> affine (a, d) ----------------
__global__ void k_finalize(const float* __restrict__ sums, const float* __restrict__ sqs,
                           const float* __restrict__ g, const float* __restrict__ b,
                           float* __restrict__ aA, float* __restrict__ aD,
                           int ncols, float invM)
{
    int i = blockIdx.x * blockDim.x + threadIdx.x;
    if (i >= ncols) return;
    float mu = sums[i] * invM;
    float var = sqs[i] * invM - mu * mu;
    float rs = rsqrtf(var + 1e-5f);
    float a = g[i] * rs;
    aA[i] = a;
    aD[i] = fmaf(-mu, a, b[i]);
}

// ---------------- final normalize + ReLU -> d_out ----------------
__global__ void k_norm(const float* __restrict__ in,
                       const float* __restrict__ aA, const float* __restrict__ aD,
                       float* __restrict__ out, int M)
{
    int idx = blockIdx.x * blockDim.x + threadIdx.x;
    int total = M * 32;
    if (idx >= total) return;
    int c4 = (idx & 31) * 4;
    float4 v = ((const float4*)in)[idx];
    float4 a = *(const float4*)(aA + c4);
    float4 d = *(const float4*)(aD + c4);
    v.x = fmaxf(fmaf(a.x, v.x, d.x), 0.f);
    v.y = fmaxf(fmaf(a.y, v.y, d.y), 0.f);
    v.z = fmaxf(fmaf(a.z, v.z, d.z), 0.f);
    v.w = fmaxf(fmaf(a.w, v.w, d.w), 0.f);
    ((float4*)out)[idx] = v;
}

// ---------------- host launch ----------------
extern "C" void kernel_launch(void* const* d_in, const int* in_sizes, int n_in,
                              void* d_out, int out_size)
{
    const float* node   = (const float*)d_in[0];
    const float* edge   = (const float*)d_in[1];
    const int*   ep     = (const int*)  d_in[2];
    const float* W_lvl1 = (const float*)d_in[3];
    const float* gl1    = (const float*)d_in[4];
    const float* bl1    = (const float*)d_in[5];
    const float* W_n1   = (const float*)d_in[6];
    const float* gn1    = (const float*)d_in[7];
    const float* bn1    = (const float*)d_in[8];
    const float* W_n2   = (const float*)d_in[9];
    const float* gn2    = (const float*)d_in[10];
    const float* bn2    = (const float*)d_in[11];
    const float* W_e1   = (const float*)d_in[12];
    const float* ge1    = (const float*)d_in[13];
    const float* be1    = (const float*)d_in[14];
    const float* W_e2   = (const float*)d_in[15];
    const float* ge2    = (const float*)d_in[16];
    const float* be2    = (const float*)d_in[17];
    const float* eps1   = (const float*)d_in[18];
    const float* eps2   = (const float*)d_in[19];
    float* outp = (float*)d_out;

    const int Cc = in_sizes[4];                  // 128
    const int Nn = in_sizes[0] / Cc;
    const int Ee = in_sizes[1] / Cc;

    float *hpre, *hidden, *lvl, *outpre_n, *ssum, *ssq, *affA, *affD;
    cudaGetSymbolAddress((void**)&hpre,     g_hpre);
    cudaGetSymbolAddress((void**)&hidden,   g_hidden);
    cudaGetSymbolAddress((void**)&lvl,      g_lvl);
    cudaGetSymbolAddress((void**)&outpre_n, g_outpre_n);
    cudaGetSymbolAddress((void**)&ssum,     g_stat_sum);
    cudaGetSymbolAddress((void**)&ssq,      g_stat_sq);
    cudaGetSymbolAddress((void**)&affA,     g_aff_a);
    cudaGetSymbolAddress((void**)&affD,     g_aff_d);

    cudaMemsetAsync(lvl,  0, (size_t)Nn * Cc * sizeof(float), 0);
    cudaMemsetAsync(ssum, 0, 5 * 256 * sizeof(float), 0);
    cudaMemsetAsync(ssq,  0, 5 * 256 * sizeof(float), 0);

    const int TPB = 256;
    const int eThreads = Ee * 32;
    const int nThreads = Nn * 32;

    // 1) lvl1 GEMM (gather-concat fused) + stats stage 0
    dim3 gE((Ee + BM - 1) / BM, 1);
    k_gemm<<<gE, TPB>>>(node, edge, W_lvl1, nullptr, nullptr, nullptr, ep, Ee,
                        hpre, ssum + 0, ssq + 0, Ee, 256, 128, 0);
    k_finalize<<<1, 256>>>(ssum + 0, ssq + 0, gl1, bl1, affA + 0, affD + 0, 128, 1.f / (float)Ee);

    // 2) scatter-add h (affine+relu fused) into lvl_aggr
    k_scatter<<<(eThreads + TPB - 1) / TPB, TPB>>>(ep, Ee);

    // 3) node MLP
    dim3 gN1((Nn + BM - 1) / BM, 2);
    k_gemm<<<gN1, TPB>>>(node, lvl, W_n1, eps1, nullptr, nullptr, nullptr, 0,
                         hidden, ssum + 256, ssq + 256, Nn, 128, 256, 1);
    k_finalize<<<1, 256>>>(ssum + 256, ssq + 256, gn1, bn1, affA + 256, affD + 256, 256, 1.f / (float)Nn);
    dim3 gN2((Nn + BM - 1) / BM, 1);
    k_gemm<<<gN2, TPB>>>(hidden, nullptr, W_n2, nullptr, affA + 256, affD + 256, nullptr, 0,
                         outpre_n, ssum + 512, ssq + 512, Nn, 256, 128, 2);
    k_finalize<<<1, 256>>>(ssum + 512, ssq + 512, gn2, bn2, affA + 512, affD + 512, 128, 1.f / (float)Nn);
    k_norm<<<(nThreads + TPB - 1) / TPB, TPB>>>(outpre_n, affA + 512, affD + 512, outp, Nn);

    // 4) edge MLP (gather fused into A-load, mode 3)
    dim3 gE1((Ee + BM - 1) / BM, 2);
    k_gemm<<<gE1, TPB>>>(edge, node, W_e1, eps2, nullptr, nullptr, ep, Ee,
                         hidden, ssum + 768, ssq + 768, Ee, 128, 256, 3);
    k_finalize<<<1, 256>>>(ssum + 768, ssq + 768, ge1, be1, affA + 768, affD + 768, 256, 1.f / (float)Ee);
    dim3 gE2((Ee + BM - 1) / BM, 1);
    k_gemm<<<gE2, TPB>>>(hidden, nullptr, W_e2, nullptr, affA + 768, affD + 768, nullptr, 0,
                         hpre, ssum + 1024, ssq + 1024, Ee, 256, 128, 2);
    k_finalize<<<1, 256>>>(ssum + 1024, ssq + 1024, ge2, be2, affA + 1024, affD + 1024, 128, 1.f / (float)Ee);
    k_norm<<<(eThreads + TPB - 1) / TPB, TPB>>>(hpre, affA + 1024, affD + 1024,
                                                outp + (size_t)Nn * Cc, Ee);
}

// round 6
// speedup vs baseline: 1.7371x; 1.0388x over previous
#include <cuda_runtime.h>
#include <cuda_bf16.h>
#include <cstdint>

// Problem-size upper bounds (fixed by the dataset)
#define MAXE 500000
#define MAXN 100000
#define CC   128

// ---------------- scratch (device globals; no allocation) ----------------
__device__ float g_hpre[(size_t)MAXE * CC];          // lvl1 pre-BN (scatter input)
__device__ float g_epre[(size_t)MAXE * CC];          // edge MLP2 out pre-BN
__device__ float g_hidden[(size_t)MAXE * 2 * CC];    // edge MLP hidden
__device__ float g_hidden_n[(size_t)MAXN * 2 * CC];  // node MLP hidden
__device__ float g_lvl[(size_t)MAXN * CC];           // lvl_aggr [N,128]
__device__ float g_outpre_n[(size_t)MAXN * CC];      // node out pre-BN
__device__ float g_stat_sum[5 * 256];
__device__ float g_stat_sq[5 * 256];
__device__ float g_aff_a[5 * 256];
__device__ float g_aff_d[5 * 256];

__device__ __forceinline__ uint32_t f2tf32(float x) {
    uint32_t r;
    asm("cvt.rna.tf32.f32 %0, %1;" : "=r"(r) : "f"(x));
    return r;
}

// ---------------- scatter: lvl_aggr[s] += h, lvl_aggr[t] += h ----------------
// h = relu(a*h_pre + d) computed on the fly; vectorized red.v4
__global__ void k_scatter(const int* __restrict__ ep, int E)
{
    int idx = blockIdx.x * blockDim.x + threadIdx.x;
    int total = E * 32;
    if (idx >= total) return;
    int e = idx >> 5;
    int c4 = (idx & 31) * 4;
    float4 v = *(const float4*)(g_hpre + (size_t)e * CC + c4);
    float4 a = *(const float4*)(g_aff_a + c4);
    float4 d = *(const float4*)(g_aff_d + c4);
    v.x = fmaxf(fmaf(a.x, v.x, d.x), 0.f);
    v.y = fmaxf(fmaf(a.y, v.y, d.y), 0.f);
    v.z = fmaxf(fmaf(a.z, v.z, d.z), 0.f);
    v.w = fmaxf(fmaf(a.w, v.w, d.w), 0.f);
    int s = ep[e];
    int t = ep[E + e];
    float* ps = g_lvl + (size_t)s * CC + c4;
    float* pt = g_lvl + (size_t)t * CC + c4;
    asm volatile("red.global.add.v4.f32 [%0], {%1,%2,%3,%4};"
                 :: "l"(ps), "f"(v.x), "f"(v.y), "f"(v.z), "f"(v.w) : "memory");
    asm volatile("red.global.add.v4.f32 [%0], {%1,%2,%3,%4};"
                 :: "l"(pt), "f"(v.x), "f"(v.y), "f"(v.z), "f"(v.w) : "memory");
}

// ---------------- fused tf32 tensor-core GEMM + BN-stats epilogue ----------------
// Block tile 128x128, BK=16, 256 threads (8 warps), warp tile 64x32 (m16n8k8).
// Double-buffered smem; global loads for iter i+1 overlap MMAs of iter i.
// mode 0: A = concat(node[s]+node[t], edge[row])     (K=256, gathers)
// mode 1: A = (1+*eps)*A0[row] + A1[row]             (K=128)
// mode 2: A = relu(aIn[k]*A0[row,k] + dIn[k])        (row stride K)
// mode 3: A = (1+*eps)*edge[row] + node[s]+node[t]   (K=128, gathers)
#define BM 128
#define BN 128
#define BK 16

__global__ __launch_bounds__(256, 2) void k_gemm(
    const float* __restrict__ A0, const float* __restrict__ A1,
    const float* __restrict__ W,  const float* __restrict__ eps_ptr,
    const float* __restrict__ aIn, const float* __restrict__ dIn,
    const int* __restrict__ ep, int E,
    float* __restrict__ out, float* __restrict__ statSum, float* __restrict__ statSq,
    int M, int K, int NC, int mode)
{
    __shared__ uint32_t As[2][BM][BK + 4];
    __shared__ uint32_t Bs[2][BK][BN + 8];
    __shared__ float ssum[BN];
    __shared__ float ssq[BN];

    const int tid    = threadIdx.x;
    const int warpId = tid >> 5;
    const int lane   = tid & 31;
    const int g      = lane >> 2;
    const int t      = lane & 3;
    const int m0w    = (warpId >> 2) * 64;
    const int n0w    = (warpId & 3) * 32;
    const int m_blk  = blockIdx.x * BM;
    const int nb     = blockIdx.y * BN;

    int aRowL[2], aRowG[2], sIdx[2], tIdx[2];
    const int k4 = (tid & 3) * 4;
#pragma unroll
    for (int j = 0; j < 2; j++) {
        int f = tid + j * 256;
        aRowL[j] = f >> 2;
        int gm = m_blk + aRowL[j];
        aRowG[j] = gm;
        sIdx[j] = 0; tIdx[j] = 0;
        if ((mode == 0 || mode == 3) && gm < M) {
            sIdx[j] = ep[gm];
            tIdx[j] = ep[E + gm];
        }
    }
    int bRowL[2], bColL[2];
#pragma unroll
    for (int j = 0; j < 2; j++) {
        int f = tid + j * 256;
        bRowL[j] = f >> 5;
        bColL[j] = (f & 31) * 4;
    }

    float epsv = 0.f;
    if (mode == 1 || mode == 3) epsv = 1.f + __ldg(eps_ptr);

    float acc[4][4][4];
#pragma unroll
    for (int i = 0; i < 4; i++)
#pragma unroll
        for (int j = 0; j < 4; j++)
#pragma unroll
            for (int c = 0; c < 4; c++) acc[i][j][c] = 0.f;

    const int nIter = K / BK;
    float4 aPre[2], bPre[2];

    auto loadTile = [&](int it) {
#pragma unroll
        for (int j = 0; j < 2; j++) {
            float4 av = make_float4(0.f, 0.f, 0.f, 0.f);
            int gm = aRowG[j];
            if (gm < M) {
                int gk = it * BK + k4;
                if (mode == 0) {
                    if (gk < 128) {
                        float4 x = *(const float4*)(A0 + (size_t)sIdx[j] * 128 + gk);
                        float4 y = *(const float4*)(A0 + (size_t)tIdx[j] * 128 + gk);
                        av.x = x.x + y.x; av.y = x.y + y.y;
                        av.z = x.z + y.z; av.w = x.w + y.w;
                    } else {
                        av = *(const float4*)(A1 + (size_t)gm * 128 + (gk - 128));
                    }
                } else if (mode == 1) {
                    float4 x = *(const float4*)(A0 + (size_t)gm * 128 + gk);
                    float4 y = *(const float4*)(A1 + (size_t)gm * 128 + gk);
                    av.x = fmaf(epsv, x.x, y.x);
                    av.y = fmaf(epsv, x.y, y.y);
                    av.z = fmaf(epsv, x.z, y.z);
                    av.w = fmaf(epsv, x.w, y.w);
                } else if (mode == 2) {
                    float4 x = *(const float4*)(A0 + (size_t)gm * K + gk);
                    float4 a = *(const float4*)(aIn + gk);
                    float4 d = *(const float4*)(dIn + gk);
                    av.x = fmaxf(fmaf(a.x, x.x, d.x), 0.f);
                    av.y = fmaxf(fmaf(a.y, x.y, d.y), 0.f);
                    av.z = fmaxf(fmaf(a.z, x.z, d.z), 0.f);
                    av.w = fmaxf(fmaf(a.w, x.w, d.w), 0.f);
                } else { // mode 3
                    float4 eV = *(const float4*)(A0 + (size_t)gm * 128 + gk);
                    float4 x = *(const float4*)(A1 + (size_t)sIdx[j] * 128 + gk);
                    float4 y = *(const float4*)(A1 + (size_t)tIdx[j] * 128 + gk);
                    av.x = fmaf(epsv, eV.x, x.x + y.x);
                    av.y = fmaf(epsv, eV.y, x.y + y.y);
                    av.z = fmaf(epsv, eV.z, x.z + y.z);
                    av.w = fmaf(epsv, eV.w, x.w + y.w);
                }
            }
            aPre[j] = av;
            bPre[j] = *(const float4*)(W + (size_t)(it * BK + bRowL[j]) * NC + nb + bColL[j]);
        }
    };
    auto storeTile = [&](int buf) {
#pragma unroll
        for (int j = 0; j < 2; j++) {
            *(uint4*)&As[buf][aRowL[j]][k4] =
                make_uint4(f2tf32(aPre[j].x), f2tf32(aPre[j].y),
                           f2tf32(aPre[j].z), f2tf32(aPre[j].w));
            *(uint4*)&Bs[buf][bRowL[j]][bColL[j]] =
                make_uint4(f2tf32(bPre[j].x), f2tf32(bPre[j].y),
                           f2tf32(bPre[j].z), f2tf32(bPre[j].w));
        }
    };

    loadTile(0);
    storeTile(0);
    __syncthreads();

    for (int it = 0; it < nIter; it++) {
        const int buf = it & 1;
        if (it + 1 < nIter) loadTile(it + 1);

#pragma unroll
        for (int ks = 0; ks < 2; ks++) {
            const int kb = ks * 8;
            uint32_t af[4][4];
            uint32_t bf[4][2];
#pragma unroll
            for (int mt = 0; mt < 4; mt++) {
                int r = m0w + mt * 16 + g;
                af[mt][0] = As[buf][r][kb + t];
                af[mt][1] = As[buf][r + 8][kb + t];
                af[mt][2] = As[buf][r][kb + t + 4];
                af[mt][3] = As[buf][r + 8][kb + t + 4];
            }
#pragma unroll
            for (int nt = 0; nt < 4; nt++) {
                int c = n0w + nt * 8 + g;
                bf[nt][0] = Bs[buf][kb + t][c];
                bf[nt][1] = Bs[buf][kb + t + 4][c];
            }
#pragma unroll
            for (int mt = 0; mt < 4; mt++)
#pragma unroll
                for (int nt = 0; nt < 4; nt++) {
                    asm volatile(
                        "mma.sync.aligned.m16n8k8.row.col.f32.tf32.tf32.f32 "
                        "{%0,%1,%2,%3}, {%4,%5,%6,%7}, {%8,%9}, {%0,%1,%2,%3};"
                        : "+f"(acc[mt][nt][0]), "+f"(acc[mt][nt][1]),
                          "+f"(acc[mt][nt][2]), "+f"(acc[mt][nt][3])
                        : "r"(af[mt][0]), "r"(af[mt][1]), "r"(af[mt][2]), "r"(af[mt][3]),
                          "r"(bf[nt][0]), "r"(bf[nt][1]));
                }
        }

        if (it + 1 < nIter) storeTile(buf ^ 1);
        __syncthreads();
    }

    // ---- epilogue: per-column stats + store ----
    for (int i = tid; i < BN; i += 256) { ssum[i] = 0.f; ssq[i] = 0.f; }
    __syncthreads();

#pragma unroll
    for (int nt = 0; nt < 4; nt++) {
        float se = 0.f, qe = 0.f, so = 0.f, qo = 0.f;
#pragma unroll
        for (int mt = 0; mt < 4; mt++) {
            float c0 = acc[mt][nt][0], c1 = acc[mt][nt][1];
            float c2 = acc[mt][nt][2], c3 = acc[mt][nt][3];
            se += c0 + c2; qe += c0 * c0 + c2 * c2;
            so += c1 + c3; qo += c1 * c1 + c3 * c3;
        }
        int ce = n0w + nt * 8 + 2 * t;
        atomicAdd(&ssum[ce], se);     atomicAdd(&ssq[ce], qe);
        atomicAdd(&ssum[ce + 1], so); atomicAdd(&ssq[ce + 1], qo);
    }

#pragma unroll
    for (int mt = 0; mt < 4; mt++) {
        int r0 = m_blk + m0w + mt * 16 + g;
        int r1 = r0 + 8;
#pragma unroll
        for (int nt = 0; nt < 4; nt++) {
            int ce = n0w + nt * 8 + 2 * t;
            if (r0 < M) {
                float2 v = make_float2(acc[mt][nt][0], acc[mt][nt][1]);
                *(float2*)(out + (size_t)r0 * NC + nb + ce) = v;
            }
            if (r1 < M) {
                float2 v = make_float2(acc[mt][nt][2], acc[mt][nt][3]);
                *(float2*)(out + (size_t)r1 * NC + nb + ce) = v;
            }
        }
    }

    __syncthreads();
    for (int i = tid; i < BN; i += 256) {
        atomicAdd(&statSum[nb + i], ssum[i]);
        atomicAdd(&statSq[nb + i], ssq[i]);
    }
}

// ---------------- finalize BN stats -> affine (a, d) ----------------
__global__ void k_finalize(const float* __restrict__ sums, const float* __restrict__ sqs,
                           const float* __restrict__ g, const float* __restrict__ b,
                           float* __restrict__ aA, float* __restrict__ aD,
                           int ncols, float invM)
{
    int i = blockIdx.x * blockDim.x + threadIdx.x;
    if (i >= ncols) return;
    float mu = sums[i] * invM;
    float var = sqs[i] * invM - mu * mu;
    float rs = rsqrtf(var + 1e-5f);
    float a = g[i] * rs;
    aA[i] = a;
    aD[i] = fmaf(-mu, a, b[i]);
}

// ---------------- final normalize + ReLU -> d_out ----------------
__global__ void k_norm(const float* __restrict__ in,
                       const float* __restrict__ aA, const float* __restrict__ aD,
                       float* __restrict__ out, int M)
{
    int idx = blockIdx.x * blockDim.x + threadIdx.x;
    int total = M * 32;
    if (idx >= total) return;
    int c4 = (idx & 31) * 4;
    float4 v = ((const float4*)in)[idx];
    float4 a = *(const float4*)(aA + c4);
    float4 d = *(const float4*)(aD + c4);
    v.x = fmaxf(fmaf(a.x, v.x, d.x), 0.f);
    v.y = fmaxf(fmaf(a.y, v.y, d.y), 0.f);
    v.z = fmaxf(fmaf(a.z, v.z, d.z), 0.f);
    v.w = fmaxf(fmaf(a.w, v.w, d.w), 0.f);
    ((float4*)out)[idx] = v;
}

// ---------------- host launch ----------------
extern "C" void kernel_launch(void* const* d_in, const int* in_sizes, int n_in,
                              void* d_out, int out_size)
{
    const float* node   = (const float*)d_in[0];
    const float* edge   = (const float*)d_in[1];
    const int*   ep     = (const int*)  d_in[2];
    const float* W_lvl1 = (const float*)d_in[3];
    const float* gl1    = (const float*)d_in[4];
    const float* bl1    = (const float*)d_in[5];
    const float* W_n1   = (const float*)d_in[6];
    const float* gn1    = (const float*)d_in[7];
    const float* bn1    = (const float*)d_in[8];
    const float* W_n2   = (const float*)d_in[9];
    const float* gn2    = (const float*)d_in[10];
    const float* bn2    = (const float*)d_in[11];
    const float* W_e1   = (const float*)d_in[12];
    const float* ge1    = (const float*)d_in[13];
    const float* be1    = (const float*)d_in[14];
    const float* W_e2   = (const float*)d_in[15];
    const float* ge2    = (const float*)d_in[16];
    const float* be2    = (const float*)d_in[17];
    const float* eps1   = (const float*)d_in[18];
    const float* eps2   = (const float*)d_in[19];
    float* outp = (float*)d_out;

    const int Cc = in_sizes[4];                  // 128
    const int Nn = in_sizes[0] / Cc;
    const int Ee = in_sizes[1] / Cc;

    float *hpre, *epre, *hidden, *hidden_n, *lvl, *outpre_n, *ssum, *ssq, *affA, *affD;
    cudaGetSymbolAddress((void**)&hpre,     g_hpre);
    cudaGetSymbolAddress((void**)&epre,     g_epre);
    cudaGetSymbolAddress((void**)&hidden,   g_hidden);
    cudaGetSymbolAddress((void**)&hidden_n, g_hidden_n);
    cudaGetSymbolAddress((void**)&lvl,      g_lvl);
    cudaGetSymbolAddress((void**)&outpre_n, g_outpre_n);
    cudaGetSymbolAddress((void**)&ssum,     g_stat_sum);
    cudaGetSymbolAddress((void**)&ssq,      g_stat_sq);
    cudaGetSymbolAddress((void**)&affA,     g_aff_a);
    cudaGetSymbolAddress((void**)&affD,     g_aff_d);

    // one-time stream/event setup (not device memory; deterministic thereafter)
    static cudaStream_t s1 = nullptr;
    static cudaEvent_t evFork = nullptr, evJoin = nullptr;
    if (!s1) {
        cudaStreamCreateWithFlags(&s1, cudaStreamNonBlocking);
        cudaEventCreateWithFlags(&evFork, cudaEventDisableTiming);
        cudaEventCreateWithFlags(&evJoin, cudaEventDisableTiming);
    }

    cudaMemsetAsync(lvl,  0, (size_t)Nn * Cc * sizeof(float), 0);
    cudaMemsetAsync(ssum, 0, 5 * 256 * sizeof(float), 0);
    cudaMemsetAsync(ssq,  0, 5 * 256 * sizeof(float), 0);

    const int TPB = 256;
    const int eThreads = Ee * 32;
    const int nThreads = Nn * 32;

    // fork: edge chain on s1, node chain on stream 0
    cudaEventRecord(evFork, 0);
    cudaStreamWaitEvent(s1, evFork, 0);

    // ===== stream 0: lvl1 -> scatter -> node MLP =====
    dim3 gE((Ee + BM - 1) / BM, 1);
    k_gemm<<<gE, TPB, 0, 0>>>(node, edge, W_lvl1, nullptr, nullptr, nullptr, ep, Ee,
                              hpre, ssum + 0, ssq + 0, Ee, 256, 128, 0);
    k_finalize<<<1, 256, 0, 0>>>(ssum + 0, ssq + 0, gl1, bl1, affA + 0, affD + 0,
                                 128, 1.f / (float)Ee);
    k_scatter<<<(eThreads + TPB - 1) / TPB, TPB, 0, 0>>>(ep, Ee);

    dim3 gN1((Nn + BM - 1) / BM, 2);
    k_gemm<<<gN1, TPB, 0, 0>>>(node, lvl, W_n1, eps1, nullptr, nullptr, nullptr, 0,
                               hidden_n, ssum + 256, ssq + 256, Nn, 128, 256, 1);
    k_finalize<<<1, 256, 0, 0>>>(ssum + 256, ssq + 256, gn1, bn1, affA + 256, affD + 256,
                                 256, 1.f / (float)Nn);
    dim3 gN2((Nn + BM - 1) / BM, 1);
    k_gemm<<<gN2, TPB, 0, 0>>>(hidden_n, nullptr, W_n2, nullptr, affA + 256, affD + 256,
                               nullptr, 0,
                               outpre_n, ssum + 512, ssq + 512, Nn, 256, 128, 2);
    k_finalize<<<1, 256, 0, 0>>>(ssum + 512, ssq + 512, gn2, bn2, affA + 512, affD + 512,
                                 128, 1.f / (float)Nn);
    k_norm<<<(nThreads + TPB - 1) / TPB, TPB, 0, 0>>>(outpre_n, affA + 512, affD + 512,
                                                      outp, Nn);

    // ===== stream s1: edge MLP (independent of lvl1/scatter) =====
    dim3 gE1((Ee + BM - 1) / BM, 2);
    k_gemm<<<gE1, TPB, 0, s1>>>(edge, node, W_e1, eps2, nullptr, nullptr, ep, Ee,
                                hidden, ssum + 768, ssq + 768, Ee, 128, 256, 3);
    k_finalize<<<1, 256, 0, s1>>>(ssum + 768, ssq + 768, ge1, be1, affA + 768, affD + 768,
                                  256, 1.f / (float)Ee);
    dim3 gE2((Ee + BM - 1) / BM, 1);
    k_gemm<<<gE2, TPB, 0, s1>>>(hidden, nullptr, W_e2, nullptr, affA + 768, affD + 768,
                                nullptr, 0,
                                epre, ssum + 1024, ssq + 1024, Ee, 256, 128, 2);
    k_finalize<<<1, 256, 0, s1>>>(ssum + 1024, ssq + 1024, ge2, be2, affA + 1024, affD + 1024,
                                  128, 1.f / (float)Ee);
    k_norm<<<(eThreads + TPB - 1) / TPB, TPB, 0, s1>>>(epre, affA + 1024, affD + 1024,
                                                       outp + (size_t)Nn * Cc, Ee);

    // join
    cudaEventRecord(evJoin, s1);
    cudaStreamWaitEvent(0, evJoin, 0);
}

// round 9
// speedup vs baseline: 1.7704x; 1.0191x over previous
#include <cuda_runtime.h>
#include <cuda_bf16.h>
#include <cstdint>

// Problem-size upper bounds (fixed by the dataset)
#define MAXE 500000
#define MAXN 100000
#define CC   128

// ---------------- scratch (device globals; no allocation) ----------------
__device__ float g_hpre[(size_t)MAXE * CC];          // lvl1 pre-BN (scatter input)
__device__ float g_epre[(size_t)MAXE * CC];          // edge MLP2 out pre-BN
__device__ float g_hidden[(size_t)MAXE * 2 * CC];    // edge MLP hidden
__device__ float g_hidden_n[(size_t)MAXN * 2 * CC];  // node MLP hidden
__device__ float g_lvl[(size_t)MAXN * CC];           // lvl_aggr [N,128]
__device__ float g_outpre_n[(size_t)MAXN * CC];      // node out pre-BN
__device__ float g_stat_sum[5 * 256];
__device__ float g_stat_sq[5 * 256];
__device__ float g_aff_a[5 * 256];
__device__ float g_aff_d[5 * 256];

__device__ __forceinline__ uint32_t f2tf32(float x) {
    uint32_t r;
    asm("cvt.rna.tf32.f32 %0, %1;" : "=r"(r) : "f"(x));
    return r;
}

// ---------------- scatter: lvl_aggr[s] += h, lvl_aggr[t] += h ----------------
__global__ void k_scatter(const int* __restrict__ ep, int E)
{
    int idx = blockIdx.x * blockDim.x + threadIdx.x;
    int total = E * 32;
    if (idx >= total) return;
    int e = idx >> 5;
    int c4 = (idx & 31) * 4;
    float4 v = *(const float4*)(g_hpre + (size_t)e * CC + c4);
    float4 a = *(const float4*)(g_aff_a + c4);
    float4 d = *(const float4*)(g_aff_d + c4);
    v.x = fmaxf(fmaf(a.x, v.x, d.x), 0.f);
    v.y = fmaxf(fmaf(a.y, v.y, d.y), 0.f);
    v.z = fmaxf(fmaf(a.z, v.z, d.z), 0.f);
    v.w = fmaxf(fmaf(a.w, v.w, d.w), 0.f);
    int s = ep[e];
    int t = ep[E + e];
    float* ps = g_lvl + (size_t)s * CC + c4;
    float* pt = g_lvl + (size_t)t * CC + c4;
    asm volatile("red.global.add.v4.f32 [%0], {%1,%2,%3,%4};"
                 :: "l"(ps), "f"(v.x), "f"(v.y), "f"(v.z), "f"(v.w) : "memory");
    asm volatile("red.global.add.v4.f32 [%0], {%1,%2,%3,%4};"
                 :: "l"(pt), "f"(v.x), "f"(v.y), "f"(v.z), "f"(v.w) : "memory");
}

// ---------------- fused tf32 tensor-core GEMM + BN-stats epilogue ----------------
// Block tile 128x128, BK=16, 512 threads (16 warps, 4x4), warp tile 32x32.
// Double-buffered smem; register prefetch of iter i+1 overlaps MMAs of iter i.
// Per-element math identical to the round-6 kernel (combine in fp32 at load,
// single tf32 rounding, sequential K accumulation).
// mode 0: A = concat(node[s]+node[t], edge[row])     (K=256, gathers)
// mode 1: A = (1+*eps)*A0[row] + A1[row]             (K=128)
// mode 2: A = relu(aIn[k]*A0[row,k] + dIn[k])        (row stride K)
// mode 3: A = (1+*eps)*edge[row] + node[s]+node[t]   (K=128, gathers)
#define BM 128
#define BN 128
#define BK 16

__global__ __launch_bounds__(512, 2) void k_gemm(
    const float* __restrict__ A0, const float* __restrict__ A1,
    const float* __restrict__ W,  const float* __restrict__ eps_ptr,
    const float* __restrict__ aIn, const float* __restrict__ dIn,
    const int* __restrict__ ep, int E,
    float* __restrict__ out, float* __restrict__ statSum, float* __restrict__ statSq,
    int M, int K, int NC, int mode)
{
    __shared__ uint32_t As[2][BM][BK + 4];   // 2*128*20*4 = 20.5 KB
    __shared__ uint32_t Bs[2][BK][BN + 8];   // 2*16*136*4 = 17.4 KB
    __shared__ float ssum[BN];
    __shared__ float ssq[BN];

    const int tid    = threadIdx.x;
    const int warpId = tid >> 5;             // 0..15
    const int lane   = tid & 31;
    const int g      = lane >> 2;
    const int t      = lane & 3;
    const int m0w    = (warpId >> 2) * 32;   // 4 warp-rows
    const int n0w    = (warpId & 3) * 32;    // 4 warp-cols
    const int m_blk  = blockIdx.x * BM;
    const int nb     = blockIdx.y * BN;

    // A-loader geometry: 512 threads cover 128x16 in one float4 each
    const int aRowL = tid >> 2;              // 0..127
    const int k4    = (tid & 3) * 4;         // 0,4,8,12
    const int aRowG = m_blk + aRowL;
    int sIdx = 0, tIdx = 0;
    if ((mode == 0 || mode == 3) && aRowG < M) {
        sIdx = ep[aRowG];
        tIdx = ep[E + aRowG];
    }
    // B-loader geometry: 512 threads cover 16x128 in one float4 each
    const int bRowL = tid >> 5;              // 0..15
    const int bColL = (tid & 31) * 4;        // 0..124

    float epsv = 0.f;
    if (mode == 1 || mode == 3) epsv = 1.f + __ldg(eps_ptr);

    float acc[2][4][4];
#pragma unroll
    for (int i = 0; i < 2; i++)
#pragma unroll
        for (int j = 0; j < 4; j++)
#pragma unroll
            for (int c = 0; c < 4; c++) acc[i][j][c] = 0.f;

    const int nIter = K / BK;
    float4 aPre, bPre;

    auto loadTile = [&](int it) {
        float4 av = make_float4(0.f, 0.f, 0.f, 0.f);
        if (aRowG < M) {
            int gk = it * BK + k4;
            if (mode == 0) {
                if (gk < 128) {
                    float4 x = *(const float4*)(A0 + (size_t)sIdx * 128 + gk);
                    float4 y = *(const float4*)(A0 + (size_t)tIdx * 128 + gk);
                    av.x = x.x + y.x; av.y = x.y + y.y;
                    av.z = x.z + y.z; av.w = x.w + y.w;
                } else {
                    av = *(const float4*)(A1 + (size_t)aRowG * 128 + (gk - 128));
                }
            } else if (mode == 1) {
                float4 x = *(const float4*)(A0 + (size_t)aRowG * 128 + gk);
                float4 y = *(const float4*)(A1 + (size_t)aRowG * 128 + gk);
                av.x = fmaf(epsv, x.x, y.x);
                av.y = fmaf(epsv, x.y, y.y);
                av.z = fmaf(epsv, x.z, y.z);
                av.w = fmaf(epsv, x.w, y.w);
            } else if (mode == 2) {
                float4 x = *(const float4*)(A0 + (size_t)aRowG * K + gk);
                float4 a = *(const float4*)(aIn + gk);
                float4 d = *(const float4*)(dIn + gk);
                av.x = fmaxf(fmaf(a.x, x.x, d.x), 0.f);
                av.y = fmaxf(fmaf(a.y, x.y, d.y), 0.f);
                av.z = fmaxf(fmaf(a.z, x.z, d.z), 0.f);
                av.w = fmaxf(fmaf(a.w, x.w, d.w), 0.f);
            } else { // mode 3
                float4 eV = *(const float4*)(A0 + (size_t)aRowG * 128 + gk);
                float4 x = *(const float4*)(A1 + (size_t)sIdx * 128 + gk);
                float4 y = *(const float4*)(A1 + (size_t)tIdx * 128 + gk);
                av.x = fmaf(epsv, eV.x, x.x + y.x);
                av.y = fmaf(epsv, eV.y, x.y + y.y);
                av.z = fmaf(epsv, eV.z, x.z + y.z);
                av.w = fmaf(epsv, eV.w, x.w + y.w);
            }
        }
        aPre = av;
        bPre = *(const float4*)(W + (size_t)(it * BK + bRowL) * NC + nb + bColL);
    };
    auto storeTile = [&](int buf) {
        *(uint4*)&As[buf][aRowL][k4] =
            make_uint4(f2tf32(aPre.x), f2tf32(aPre.y), f2tf32(aPre.z), f2tf32(aPre.w));
        *(uint4*)&Bs[buf][bRowL][bColL] =
            make_uint4(f2tf32(bPre.x), f2tf32(bPre.y), f2tf32(bPre.z), f2tf32(bPre.w));
    };

    loadTile(0);
    storeTile(0);
    __syncthreads();

    for (int it = 0; it < nIter; it++) {
        const int buf = it & 1;
        if (it + 1 < nIter) loadTile(it + 1);   // overlap with MMAs below

#pragma unroll
        for (int ks = 0; ks < 2; ks++) {
            const int kb = ks * 8;
            uint32_t af[2][4];
            uint32_t bf[4][2];
#pragma unroll
            for (int mt = 0; mt < 2; mt++) {
                int r = m0w + mt * 16 + g;
                af[mt][0] = As[buf][r][kb + t];
                af[mt][1] = As[buf][r + 8][kb + t];
                af[mt][2] = As[buf][r][kb + t + 4];
                af[mt][3] = As[buf][r + 8][kb + t + 4];
            }
#pragma unroll
            for (int nt = 0; nt < 4; nt++) {
                int c = n0w + nt * 8 + g;
                bf[nt][0] = Bs[buf][kb + t][c];
                bf[nt][1] = Bs[buf][kb + t + 4][c];
            }
#pragma unroll
            for (int mt = 0; mt < 2; mt++)
#pragma unroll
                for (int nt = 0; nt < 4; nt++) {
                    asm volatile(
                        "mma.sync.aligned.m16n8k8.row.col.f32.tf32.tf32.f32 "
                        "{%0,%1,%2,%3}, {%4,%5,%6,%7}, {%8,%9}, {%0,%1,%2,%3};"
                        : "+f"(acc[mt][nt][0]), "+f"(acc[mt][nt][1]),
                          "+f"(acc[mt][nt][2]), "+f"(acc[mt][nt][3])
                        : "r"(af[mt][0]), "r"(af[mt][1]), "r"(af[mt][2]), "r"(af[mt][3]),
                          "r"(bf[nt][0]), "r"(bf[nt][1]));
                }
        }

        if (it + 1 < nIter) storeTile(buf ^ 1);
        __syncthreads();
    }

    // ---- epilogue: per-column stats + store ----
    for (int i = tid; i < BN; i += 512) { ssum[i] = 0.f; ssq[i] = 0.f; }
    __syncthreads();

#pragma unroll
    for (int nt = 0; nt < 4; nt++) {
        float se = 0.f, qe = 0.f, so = 0.f, qo = 0.f;
#pragma unroll
        for (int mt = 0; mt < 2; mt++) {
            float c0 = acc[mt][nt][0], c1 = acc[mt][nt][1];
            float c2 = acc[mt][nt][2], c3 = acc[mt][nt][3];
            se += c0 + c2; qe += c0 * c0 + c2 * c2;
            so += c1 + c3; qo += c1 * c1 + c3 * c3;
        }
        int ce = n0w + nt * 8 + 2 * t;
        atomicAdd(&ssum[ce], se);     atomicAdd(&ssq[ce], qe);
        atomicAdd(&ssum[ce + 1], so); atomicAdd(&ssq[ce + 1], qo);
    }

#pragma unroll
    for (int mt = 0; mt < 2; mt++) {
        int r0 = m_blk + m0w + mt * 16 + g;
        int r1 = r0 + 8;
#pragma unroll
        for (int nt = 0; nt < 4; nt++) {
            int ce = n0w + nt * 8 + 2 * t;
            if (r0 < M) {
                float2 v = make_float2(acc[mt][nt][0], acc[mt][nt][1]);
                *(float2*)(out + (size_t)r0 * NC + nb + ce) = v;
            }
            if (r1 < M) {
                float2 v = make_float2(acc[mt][nt][2], acc[mt][nt][3]);
                *(float2*)(out + (size_t)r1 * NC + nb + ce) = v;
            }
        }
    }

    __syncthreads();
    for (int i = tid; i < BN; i += 512) {
        atomicAdd(&statSum[nb + i], ssum[i]);
        atomicAdd(&statSq[nb + i], ssq[i]);
    }
}

// ---------------- finalize BN stats -> affine (a, d) ----------------
__global__ void k_finalize(const float* __restrict__ sums, const float* __restrict__ sqs,
                           const float* __restrict__ g, const float* __restrict__ b,
                           float* __restrict__ aA, float* __restrict__ aD,
                           int ncols, float invM)
{
    int i = blockIdx.x * blockDim.x + threadIdx.x;
    if (i >= ncols) return;
    float mu = sums[i] * invM;
    float var = sqs[i] * invM - mu * mu;
    float rs = rsqrtf(var + 1e-5f);
    float a = g[i] * rs;
    aA[i] = a;
    aD[i] = fmaf(-mu, a, b[i]);
}

// ---------------- final normalize + ReLU -> d_out ----------------
__global__ void k_norm(const float* __restrict__ in,
                       const float* __restrict__ aA, const float* __restrict__ aD,
                       float* __restrict__ out, int M)
{
    int idx = blockIdx.x * blockDim.x + threadIdx.x;
    int total = M * 32;
    if (idx >= total) return;
    int c4 = (idx & 31) * 4;
    float4 v = ((const float4*)in)[idx];
    float4 a = *(const float4*)(aA + c4);
    float4 d = *(const float4*)(aD + c4);
    v.x = fmaxf(fmaf(a.x, v.x, d.x), 0.f);
    v.y = fmaxf(fmaf(a.y, v.y, d.y), 0.f);
    v.z = fmaxf(fmaf(a.z, v.z, d.z), 0.f);
    v.w = fmaxf(fmaf(a.w, v.w, d.w), 0.f);
    ((float4*)out)[idx] = v;
}

// ---------------- host launch ----------------
extern "C" void kernel_launch(void* const* d_in, const int* in_sizes, int n_in,
                              void* d_out, int out_size)
{
    const float* node   = (const float*)d_in[0];
    const float* edge   = (const float*)d_in[1];
    const int*   ep     = (const int*)  d_in[2];
    const float* W_lvl1 = (const float*)d_in[3];
    const float* gl1    = (const float*)d_in[4];
    const float* bl1    = (const float*)d_in[5];
    const float* W_n1   = (const float*)d_in[6];
    const float* gn1    = (const float*)d_in[7];
    const float* bn1    = (const float*)d_in[8];
    const float* W_n2   = (const float*)d_in[9];
    const float* gn2    = (const float*)d_in[10];
    const float* bn2    = (const float*)d_in[11];
    const float* W_e1   = (const float*)d_in[12];
    const float* ge1    = (const float*)d_in[13];
    const float* be1    = (const float*)d_in[14];
    const float* W_e2   = (const float*)d_in[15];
    const float* ge2    = (const float*)d_in[16];
    const float* be2    = (const float*)d_in[17];
    const float* eps1   = (const float*)d_in[18];
    const float* eps2   = (const float*)d_in[19];
    float* outp = (float*)d_out;

    const int Cc = in_sizes[4];                  // 128
    const int Nn = in_sizes[0] / Cc;
    const int Ee = in_sizes[1] / Cc;

    float *hpre, *epre, *hidden, *hidden_n, *lvl, *outpre_n, *ssum, *ssq, *affA, *affD;
    cudaGetSymbolAddress((void**)&hpre,     g_hpre);
    cudaGetSymbolAddress((void**)&epre,     g_epre);
    cudaGetSymbolAddress((void**)&hidden,   g_hidden);
    cudaGetSymbolAddress((void**)&hidden_n, g_hidden_n);
    cudaGetSymbolAddress((void**)&lvl,      g_lvl);
    cudaGetSymbolAddress((void**)&outpre_n, g_outpre_n);
    cudaGetSymbolAddress((void**)&ssum,     g_stat_sum);
    cudaGetSymbolAddress((void**)&ssq,      g_stat_sq);
    cudaGetSymbolAddress((void**)&affA,     g_aff_a);
    cudaGetSymbolAddress((void**)&affD,     g_aff_d);

    static bool initDone = false;
    static cudaStream_t s1 = nullptr;
    static cudaEvent_t evFork = nullptr, evJoin = nullptr;
    if (!initDone) {
        cudaStreamCreateWithFlags(&s1, cudaStreamNonBlocking);
        cudaEventCreateWithFlags(&evFork, cudaEventDisableTiming);
        cudaEventCreateWithFlags(&evJoin, cudaEventDisableTiming);
        initDone = true;
    }

    cudaMemsetAsync(lvl,  0, (size_t)Nn * Cc * sizeof(float), 0);
    cudaMemsetAsync(ssum, 0, 5 * 256 * sizeof(float), 0);
    cudaMemsetAsync(ssq,  0, 5 * 256 * sizeof(float), 0);

    const int TPB = 256;
    const int TPG = 512;
    const int eThreads = Ee * 32;
    const int nThreads = Nn * 32;
    const int gxE = (Ee + BM - 1) / BM;
    const int gxN = (Nn + BM - 1) / BM;

    // fork: edge chain on s1, node chain on stream 0
    cudaEventRecord(evFork, 0);
    cudaStreamWaitEvent(s1, evFork, 0);

    // ===== stream 0: lvl1 -> scatter -> node MLP =====
    k_gemm<<<dim3(gxE, 1), TPG, 0, 0>>>(node, edge, W_lvl1, nullptr, nullptr, nullptr, ep, Ee,
                                        hpre, ssum + 0, ssq + 0, Ee, 256, 128, 0);
    k_finalize<<<1, 256, 0, 0>>>(ssum + 0, ssq + 0, gl1, bl1, affA + 0, affD + 0,
                                 128, 1.f / (float)Ee);
    k_scatter<<<(eThreads + TPB - 1) / TPB, TPB, 0, 0>>>(ep, Ee);

    k_gemm<<<dim3(gxN, 2), TPG, 0, 0>>>(node, lvl, W_n1, eps1, nullptr, nullptr, nullptr, 0,
                                        hidden_n, ssum + 256, ssq + 256, Nn, 128, 256, 1);
    k_finalize<<<1, 256, 0, 0>>>(ssum + 256, ssq + 256, gn1, bn1, affA + 256, affD + 256,
                                 256, 1.f / (float)Nn);
    k_gemm<<<dim3(gxN, 1), TPG, 0, 0>>>(hidden_n, nullptr, W_n2, nullptr, affA + 256, affD + 256,
                                        nullptr, 0,
                                        outpre_n, ssum + 512, ssq + 512, Nn, 256, 128, 2);
    k_finalize<<<1, 256, 0, 0>>>(ssum + 512, ssq + 512, gn2, bn2, affA + 512, affD + 512,
                                 128, 1.f / (float)Nn);
    k_norm<<<(nThreads + TPB - 1) / TPB, TPB, 0, 0>>>(outpre_n, affA + 512, affD + 512,
                                                      outp, Nn);

    // ===== stream s1: edge MLP =====
    k_gemm<<<dim3(gxE, 2), TPG, 0, s1>>>(edge, node, W_e1, eps2, nullptr, nullptr, ep, Ee,
                                         hidden, ssum + 768, ssq + 768, Ee, 128, 256, 3);
    k_finalize<<<1, 256, 0, s1>>>(ssum + 768, ssq + 768, ge1, be1, affA + 768, affD + 768,
                                  256, 1.f / (float)Ee);
    k_gemm<<<dim3(gxE, 1), TPG, 0, s1>>>(hidden, nullptr, W_e2, nullptr, affA + 768, affD + 768,
                                         nullptr, 0,
                                         epre, ssum + 1024, ssq + 1024, Ee, 256, 128, 2);
    k_finalize<<<1, 256, 0, s1>>>(ssum + 1024, ssq + 1024, ge2, be2, affA + 1024, affD + 1024,
                                  128, 1.f / (float)Ee);
    k_norm<<<(eThreads + TPB - 1) / TPB, TPB, 0, s1>>>(epre, affA + 1024, affD + 1024,
                                                       outp + (size_t)Nn * Cc, Ee);

    // join
    cudaEventRecord(evJoin, s1);
    cudaStreamWaitEvent(0, evJoin, 0);
}